// round 14
// baseline (speedup 1.0000x reference)
#include <cuda_runtime.h>
#include <cuda_bf16.h>
#include <cstdint>

#define NN  100000
#define MPAD 100096          // 782 * 128
#define EE  800000
#define ETT 900000           // EE + NN self loops
#define FIN 64
#define HIDD 128

// weight hi/lo buffer offsets (elements)
#define OFF_WL1 0
#define OFF_WR1 8192
#define OFF_WL2 16384
#define OFF_WR2 32768
#define OFF_WL3 49152
#define OFF_WR3 65536
#define OFF_RTT 81920
#define OFF_RET 90112
#define WTOT    98304

// ---------------- scratch (static device globals; no runtime alloc) ----------
__device__ __nv_bfloat16 g_hh[(size_t)MPAD * HIDD];
__device__ __nv_bfloat16 g_hl[(size_t)MPAD * HIDD];
__device__ __nv_bfloat16 g_wh[WTOT];
__device__ __nv_bfloat16 g_wl[WTOT];
__device__ float g_xl[(size_t)MPAD * HIDD];
__device__ float g_xr[(size_t)MPAD * HIDD];
__device__ int   g_deg[NN];
__device__ int   g_off[NN + 1];
__device__ int   g_cur[NN];
__device__ int   g_csr[ETT];

// ---------------- helpers ----------------------------------------------------
__device__ __forceinline__ uint32_t smem_u32(const void* p) {
    uint32_t a;
    asm("{ .reg .u64 t; cvta.to.shared.u64 t, %1; cvt.u32.u64 %0, t; }" : "=r"(a) : "l"(p));
    return a;
}
__device__ __forceinline__ float warp_red_sum(float v) {
#pragma unroll
    for (int d = 16; d > 0; d >>= 1) v += __shfl_xor_sync(0xFFFFFFFFu, v, d);
    return v;
}
__device__ __forceinline__ void cp16(uint32_t dst, const void* src) {
    asm volatile("cp.async.cg.shared.global [%0], [%1], 16;" :: "r"(dst), "l"(src));
}
#define CP_COMMIT() asm volatile("cp.async.commit_group;" ::: "memory")
#define CP_WAIT1()  asm volatile("cp.async.wait_group 1;" ::: "memory")

__device__ __forceinline__ void ldsm_x4(uint32_t* r, uint32_t addr) {
    asm volatile("ldmatrix.sync.aligned.m8n8.x4.shared.b16 {%0,%1,%2,%3}, [%4];"
                 : "=r"(r[0]), "=r"(r[1]), "=r"(r[2]), "=r"(r[3]) : "r"(addr));
}
__device__ __forceinline__ void ldsm_x4_t(uint32_t* r, uint32_t addr) {
    asm volatile("ldmatrix.sync.aligned.m8n8.x4.trans.shared.b16 {%0,%1,%2,%3}, [%4];"
                 : "=r"(r[0]), "=r"(r[1]), "=r"(r[2]), "=r"(r[3]) : "r"(addr));
}
__device__ __forceinline__ void mma_bf16(float* c, const uint32_t* a, const uint32_t* b) {
    asm volatile(
        "mma.sync.aligned.m16n8k16.row.col.f32.bf16.bf16.f32 "
        "{%0,%1,%2,%3}, {%4,%5,%6,%7}, {%8,%9}, {%0,%1,%2,%3};"
        : "+f"(c[0]), "+f"(c[1]), "+f"(c[2]), "+f"(c[3])
        : "r"(a[0]), "r"(a[1]), "r"(a[2]), "r"(a[3]), "r"(b[0]), "r"(b[1]));
}
__device__ __forceinline__ void bf16_split(float v, __nv_bfloat16& h, __nv_bfloat16& l) {
    h = __float2bfloat16_rn(v);
    l = __float2bfloat16_rn(v - __bfloat162float(h));
}

// ---------------- fused weight pre-split (single launch, 8 segments) ----------
struct WSrcs { const float* p[8]; };
__global__ void split_w_all_kernel(WSrcs srcs,
                                   __nv_bfloat16* __restrict__ dh,
                                   __nv_bfloat16* __restrict__ dl) {
    int i = blockIdx.x * blockDim.x + threadIdx.x;
    if (i >= WTOT) return;
    int seg, base;
    if      (i < 8192)  { seg = 0; base = 0; }
    else if (i < 16384) { seg = 1; base = 8192; }
    else if (i < 32768) { seg = 2; base = 16384; }
    else if (i < 49152) { seg = 3; base = 32768; }
    else if (i < 65536) { seg = 4; base = 49152; }
    else if (i < 81920) { seg = 5; base = 65536; }
    else if (i < 90112) { seg = 6; base = 81920; }
    else                { seg = 7; base = 90112; }
    float v = srcs.p[seg][i - base];
    __nv_bfloat16 h, l;
    bf16_split(v, h, l);
    dh[i] = h; dl[i] = l;
}

// ---------------- bf16 split-precision tensor-core GEMM (2-stage pipeline) ----
// B fragments via ldmatrix.x4.trans over n-tile PAIRS (half the smem ops).
template <int BN>
__global__ __launch_bounds__(256)
void gemm_bf16_kernel(const __nv_bfloat16* __restrict__ Ah,
                      const __nv_bfloat16* __restrict__ Al,
                      const __nv_bfloat16* __restrict__ Wh,
                      const __nv_bfloat16* __restrict__ Wl,
                      int woff0, int woff1,
                      float* __restrict__ C0, float* __restrict__ C1,
                      int K, int cstride) {
    constexpr int BM = 128, BK = 32;
    constexpr int AST = 40;
    constexpr int BST = BN + 8;
    constexpr int WN = BN / 2;
    constexpr int NT = WN / 8;
    constexpr int NP = NT / 2;           // n-tile pairs per warp
    constexpr int SZA = BM * AST;
    constexpr int SZB = BK * BST;

    extern __shared__ __nv_bfloat16 smem[];
    uint32_t base  = smem_u32(smem);
    uint32_t pAh   = base;
    uint32_t pAl   = base + 2u * SZA * 2u;
    uint32_t pBh   = base + 4u * SZA * 2u;
    uint32_t pBl   = pBh + 2u * SZB * 2u;

    const __nv_bfloat16* W_h = Wh + (blockIdx.y ? woff1 : woff0);
    const __nv_bfloat16* W_l = Wl + (blockIdx.y ? woff1 : woff0);
    float* C = blockIdx.y ? C1 : C0;
    int bm = blockIdx.x * BM;
    int tid = threadIdx.x, wid = tid >> 5, lane = tid & 31;
    int wm = wid >> 1, wn = wid & 1;

    float acc[2][NT][4];
#pragma unroll
    for (int i = 0; i < 2; i++)
#pragma unroll
        for (int j = 0; j < NT; j++)
#pragma unroll
            for (int q = 0; q < 4; q++) acc[i][j][q] = 0.0f;

    // A ldmatrix lane mapping (x4, non-trans)
    int a_tile = lane >> 3, a_r = lane & 7;
    int a_row_off = (a_tile & 1) * 8 + a_r;
    int a_k_off   = (a_tile >> 1) * 8;
    // B ldmatrix lane mapping (x4, trans)
    int b_row = ((lane >> 3) & 1) * 8 + (lane & 7);
    int b_colq = (lane >> 4) * 8;

    int nchunks = K / BK;

    auto load_stage = [&](int st, int k0) {
        uint32_t aoffs = (uint32_t)st * SZA * 2u;
        uint32_t boffs = (uint32_t)st * SZB * 2u;
        {
            int jj = tid * 2;
#pragma unroll
            for (int q = 0; q < 2; q++) {
                int j = jj + q, row = j >> 2, seg = j & 3;
                size_t so = (size_t)(bm + row) * K + k0 + seg * 8;
                uint32_t dofs = (uint32_t)(row * AST + seg * 8) * 2;
                cp16(pAh + aoffs + dofs, Ah + so);
                cp16(pAl + aoffs + dofs, Al + so);
            }
        }
        if (BN == 128) {
            int jj = tid * 2;
#pragma unroll
            for (int q = 0; q < 2; q++) {
                int j = jj + q, row = j >> 4, seg = j & 15;
                size_t so = (size_t)(k0 + row) * BN + seg * 8;
                uint32_t dofs = (uint32_t)(row * BST + seg * 8) * 2;
                cp16(pBh + boffs + dofs, W_h + so);
                cp16(pBl + boffs + dofs, W_l + so);
            }
        } else {
            int row = tid >> 3, seg = tid & 7;
            size_t so = (size_t)(k0 + row) * BN + seg * 8;
            uint32_t dofs = (uint32_t)(row * BST + seg * 8) * 2;
            cp16(pBh + boffs + dofs, W_h + so);
            cp16(pBl + boffs + dofs, W_l + so);
        }
    };

    load_stage(0, 0);
    CP_COMMIT();

    for (int c = 0; c < nchunks; c++) {
        if (c + 1 < nchunks) load_stage((c + 1) & 1, (c + 1) * BK);
        CP_COMMIT();
        CP_WAIT1();
        __syncthreads();

        uint32_t cAh = pAh + (uint32_t)(c & 1) * SZA * 2u;
        uint32_t cAl = pAl + (uint32_t)(c & 1) * SZA * 2u;
        uint32_t cBh = pBh + (uint32_t)(c & 1) * SZB * 2u;
        uint32_t cBl = pBl + (uint32_t)(c & 1) * SZB * 2u;

#pragma unroll
        for (int kk = 0; kk < 2; kk++) {
            uint32_t ah[2][4], al[2][4];
#pragma unroll
            for (int mt = 0; mt < 2; mt++) {
                int row = wm * 32 + mt * 16 + a_row_off;
                int kc  = kk * 16 + a_k_off;
                ldsm_x4(ah[mt], cAh + (uint32_t)(row * AST + kc) * 2);
                ldsm_x4(al[mt], cAl + (uint32_t)(row * AST + kc) * 2);
            }
#pragma unroll
            for (int p = 0; p < NP; p++) {
                int krow = kk * 16 + b_row;
                int ncol = wn * WN + p * 16 + b_colq;
                uint32_t bh[4], bl[4];
                ldsm_x4_t(bh, cBh + (uint32_t)(krow * BST + ncol) * 2);
                ldsm_x4_t(bl, cBl + (uint32_t)(krow * BST + ncol) * 2);
#pragma unroll
                for (int mt = 0; mt < 2; mt++) {
                    mma_bf16(acc[mt][2 * p],     ah[mt], bh);
                    mma_bf16(acc[mt][2 * p],     ah[mt], bl);
                    mma_bf16(acc[mt][2 * p],     al[mt], bh);
                    mma_bf16(acc[mt][2 * p + 1], ah[mt], bh + 2);
                    mma_bf16(acc[mt][2 * p + 1], ah[mt], bl + 2);
                    mma_bf16(acc[mt][2 * p + 1], al[mt], bh + 2);
                }
            }
        }
        __syncthreads();
    }

    int g = lane >> 2, tg = lane & 3;
#pragma unroll
    for (int mt = 0; mt < 2; mt++) {
#pragma unroll
        for (int nt = 0; nt < NT; nt++) {
            int row0 = bm + wm * 32 + mt * 16 + g;
            int col  = wn * WN + nt * 8 + tg * 2;
            *(float2*)(C + (size_t)row0 * cstride + col) =
                make_float2(acc[mt][nt][0], acc[mt][nt][1]);
            *(float2*)(C + (size_t)(row0 + 8) * cstride + col) =
                make_float2(acc[mt][nt][2], acc[mt][nt][3]);
        }
    }
}

// ---------------- CSR build ---------------------------------------------------
__global__ void zero_int_kernel(int* p, int n) {
    int i = blockIdx.x * blockDim.x + threadIdx.x;
    if (i < n) p[i] = 0;
}

__global__ void degree_kernel(const int* __restrict__ ei, int* __restrict__ deg) {
    int e = blockIdx.x * blockDim.x + threadIdx.x;
    if (e >= ETT) return;
    int dst = (e < EE) ? ei[EE + e] : (e - EE);
    atomicAdd(&deg[dst], 1);
}

__global__ void scan_kernel(const int* __restrict__ deg, int* __restrict__ off,
                            int* __restrict__ cur, int n) {
    __shared__ int wsum[32];
    __shared__ int carry_s;
    int tid = threadIdx.x, lane = tid & 31, wid = tid >> 5;
    if (tid == 0) carry_s = 0;
    __syncthreads();
    for (int base = 0; base < n; base += 4096) {
        int i4 = base + tid * 4;
        int4 v = make_int4(0, 0, 0, 0);
        if (i4 + 3 < n) v = *(const int4*)(deg + i4);
        else {
            if (i4 + 0 < n) v.x = deg[i4 + 0];
            if (i4 + 1 < n) v.y = deg[i4 + 1];
            if (i4 + 2 < n) v.z = deg[i4 + 2];
            if (i4 + 3 < n) v.w = deg[i4 + 3];
        }
        int t = v.x + v.y + v.z + v.w;
        int x = t;
#pragma unroll
        for (int d = 1; d < 32; d <<= 1) {
            int y = __shfl_up_sync(0xFFFFFFFFu, x, d);
            if (lane >= d) x += y;
        }
        if (lane == 31) wsum[wid] = x;
        __syncthreads();
        if (wid == 0) {
            int s = wsum[lane];
#pragma unroll
            for (int d = 1; d < 32; d <<= 1) {
                int y = __shfl_up_sync(0xFFFFFFFFu, s, d);
                if (lane >= d) s += y;
            }
            wsum[lane] = s;
        }
        __syncthreads();
        int pre = (wid > 0) ? wsum[wid - 1] : 0;
        int excl = carry_s + pre + (x - t);
        if (i4 < n) {
            int4 o;
            o.x = excl; o.y = o.x + v.x; o.z = o.y + v.y; o.w = o.z + v.z;
            if (i4 + 3 < n) { *(int4*)(off + i4) = o; *(int4*)(cur + i4) = o; }
            else {
                if (i4 + 0 < n) { off[i4 + 0] = o.x; cur[i4 + 0] = o.x; }
                if (i4 + 1 < n) { off[i4 + 1] = o.y; cur[i4 + 1] = o.y; }
                if (i4 + 2 < n) { off[i4 + 2] = o.z; cur[i4 + 2] = o.z; }
                if (i4 + 3 < n) { off[i4 + 3] = o.w; cur[i4 + 3] = o.w; }
            }
        }
        int btot = wsum[31];
        __syncthreads();
        if (tid == 0) carry_s += btot;
        __syncthreads();
    }
    if (tid == 0) off[n] = carry_s;
}

__global__ void scatter_kernel(const int* __restrict__ ei, int* __restrict__ cur,
                               int* __restrict__ csr) {
    int e = blockIdx.x * blockDim.x + threadIdx.x;
    if (e >= ETT) return;
    int src, dst;
    if (e < EE) { src = ei[e]; dst = ei[EE + e]; }
    else        { src = e - EE; dst = e - EE; }
    int pos = atomicAdd(&cur[dst], 1);
    csr[pos] = src;
}

// ---------------- LN on 64-dim input -> bf16 hi/lo (stride 64) ----------------
__global__ void ln_in_kernel(const float* __restrict__ x, const float* __restrict__ g,
                             const float* __restrict__ b,
                             __nv_bfloat16* __restrict__ hh,
                             __nv_bfloat16* __restrict__ hl) {
    int w = (blockIdx.x * blockDim.x + threadIdx.x) >> 5;
    if (w >= NN) return;
    int lane = threadIdx.x & 31;
    float2 v = *(const float2*)(x + (size_t)w * FIN + lane * 2);
    float s  = warp_red_sum(v.x + v.y);
    float sq = warp_red_sum(v.x * v.x + v.y * v.y);
    float mean = s * (1.0f / FIN);
    float var  = sq * (1.0f / FIN) - mean * mean;
    float rstd = rsqrtf(var + 1e-5f);
    float2 g2 = *(const float2*)(g + lane * 2);
    float2 b2 = *(const float2*)(b + lane * 2);
    float ox = (v.x - mean) * rstd * g2.x + b2.x;
    float oy = (v.y - mean) * rstd * g2.y + b2.y;
    __nv_bfloat16 hx, lx, hy, ly;
    bf16_split(ox, hx, lx);
    bf16_split(oy, hy, ly);
    *(__nv_bfloat162*)(hh + (size_t)w * FIN + lane * 2) = __nv_bfloat162(hx, hy);
    *(__nv_bfloat162*)(hl + (size_t)w * FIN + lane * 2) = __nv_bfloat162(lx, ly);
}

// ---------------- fused GATv2 (online softmax) + LN + residual + relu ---------
// 4x unrolled edge loop (MLP=4) — best measured config (R12).
template <int H>
__global__ void gat_ln_kernel(const float* __restrict__ xl, const float* __restrict__ xr,
                              const float* __restrict__ att,
                              const int* __restrict__ off, const int* __restrict__ csr,
                              __nv_bfloat16* __restrict__ hh,
                              __nv_bfloat16* __restrict__ hl,
                              const float* __restrict__ g, const float* __restrict__ b,
                              float rscale, int do_relu) {
    int w = (blockIdx.x * blockDim.x + threadIdx.x) >> 5;
    if (w >= NN) return;
    int lane = threadIdx.x & 31;
    const int G = 32 / H;

    float4 xr4 = *(const float4*)(xr + (size_t)w * HIDD + lane * 4);
    float4 at4 = *(const float4*)(att + lane * 4);
    int e0 = off[w], e1 = off[w + 1];

    float m = -1e30f, sum = 0.f;
    float4 acc = make_float4(0.f, 0.f, 0.f, 0.f);

    auto proc = [&](const float4& v) {
        float ex = v.x + xr4.x; ex = ex > 0.f ? ex : 0.2f * ex;
        float ey = v.y + xr4.y; ey = ey > 0.f ? ey : 0.2f * ey;
        float ez = v.z + xr4.z; ez = ez > 0.f ? ez : 0.2f * ez;
        float ew = v.w + xr4.w; ew = ew > 0.f ? ew : 0.2f * ew;
        float p = ex * at4.x + ey * at4.y + ez * at4.z + ew * at4.w;
#pragma unroll
        for (int d = 1; d < G; d <<= 1) p += __shfl_xor_sync(0xFFFFFFFFu, p, d);
        float nm = fmaxf(m, p);
        float sc = __expf(m - nm);
        float f  = __expf(p - nm);
        sum = sum * sc + f;
        acc.x = acc.x * sc + f * v.x;
        acc.y = acc.y * sc + f * v.y;
        acc.z = acc.z * sc + f * v.z;
        acc.w = acc.w * sc + f * v.w;
        m = nm;
    };

    int i = e0;
    for (; i + 4 <= e1; i += 4) {
        int s0 = csr[i], s1 = csr[i + 1], s2 = csr[i + 2], s3 = csr[i + 3];
        float4 v0 = *(const float4*)(xl + (size_t)s0 * HIDD + lane * 4);
        float4 v1 = *(const float4*)(xl + (size_t)s1 * HIDD + lane * 4);
        float4 v2 = *(const float4*)(xl + (size_t)s2 * HIDD + lane * 4);
        float4 v3 = *(const float4*)(xl + (size_t)s3 * HIDD + lane * 4);
        proc(v0); proc(v1); proc(v2); proc(v3);
    }
    for (; i < e1; i++) {
        int s = csr[i];
        float4 v = *(const float4*)(xl + (size_t)s * HIDD + lane * 4);
        proc(v);
    }

    float inv = 1.0f / sum;
    float4 o = make_float4(acc.x * inv, acc.y * inv, acc.z * inv, acc.w * inv);

    size_t idx = (size_t)w * HIDD + lane * 4;
    float s1r = warp_red_sum(o.x + o.y + o.z + o.w);
    float sqr = warp_red_sum(o.x * o.x + o.y * o.y + o.z * o.z + o.w * o.w);
    float mean = s1r * (1.0f / HIDD);
    float var  = sqr * (1.0f / HIDD) - mean * mean;
    float rstd = rsqrtf(var + 1e-5f);
    float4 g4 = *(const float4*)(g + lane * 4);
    float4 b4 = *(const float4*)(b + lane * 4);
    float4 y;
    y.x = (o.x - mean) * rstd * g4.x + b4.x;
    y.y = (o.y - mean) * rstd * g4.y + b4.y;
    y.z = (o.z - mean) * rstd * g4.z + b4.z;
    y.w = (o.w - mean) * rstd * g4.w + b4.w;
    if (rscale != 0.0f) {
        __nv_bfloat162 h01 = *(__nv_bfloat162*)(hh + idx);
        __nv_bfloat162 h23 = *(__nv_bfloat162*)(hh + idx + 2);
        __nv_bfloat162 l01 = *(__nv_bfloat162*)(hl + idx);
        __nv_bfloat162 l23 = *(__nv_bfloat162*)(hl + idx + 2);
        y.x += rscale * (__bfloat162float(h01.x) + __bfloat162float(l01.x));
        y.y += rscale * (__bfloat162float(h01.y) + __bfloat162float(l01.y));
        y.z += rscale * (__bfloat162float(h23.x) + __bfloat162float(l23.x));
        y.w += rscale * (__bfloat162float(h23.y) + __bfloat162float(l23.y));
    }
    if (do_relu) {
        y.x = fmaxf(y.x, 0.f); y.y = fmaxf(y.y, 0.f);
        y.z = fmaxf(y.z, 0.f); y.w = fmaxf(y.w, 0.f);
    }
    __nv_bfloat16 hx, lx, hy, ly, hz, lz, hw, lw;
    bf16_split(y.x, hx, lx); bf16_split(y.y, hy, ly);
    bf16_split(y.z, hz, lz); bf16_split(y.w, hw, lw);
    *(__nv_bfloat162*)(hh + idx)     = __nv_bfloat162(hx, hy);
    *(__nv_bfloat162*)(hh + idx + 2) = __nv_bfloat162(hz, hw);
    *(__nv_bfloat162*)(hl + idx)     = __nv_bfloat162(lx, ly);
    *(__nv_bfloat162*)(hl + idx + 2) = __nv_bfloat162(lz, lw);
}

// ---------------- prediction heads epilogue -----------------------------------
__global__ void head_kernel(const float* __restrict__ hr, const float* __restrict__ he,
                            const float* __restrict__ rb1, const float* __restrict__ rw2,
                            const float* __restrict__ rb2,
                            const float* __restrict__ eb1, const float* __restrict__ ew2,
                            const float* __restrict__ eb2,
                            float* __restrict__ out) {
    int w = (blockIdx.x * blockDim.x + threadIdx.x) >> 5;
    if (w >= NN) return;
    int lane = threadIdx.x & 31;

    float2 a  = *(const float2*)(hr + (size_t)w * 64 + lane * 2);
    float2 b1 = *(const float2*)(rb1 + lane * 2);
    float2 w2 = *(const float2*)(rw2 + lane * 2);
    float ax = fmaxf(a.x + b1.x, 0.f), ay = fmaxf(a.y + b1.y, 0.f);
    float pr = warp_red_sum(ax * w2.x + ay * w2.y);

    float2 c  = *(const float2*)(he + (size_t)w * 64 + lane * 2);
    float2 c1 = *(const float2*)(eb1 + lane * 2);
    float2 v2 = *(const float2*)(ew2 + lane * 2);
    float cx = fmaxf(c.x + c1.x, 0.f), cy = fmaxf(c.y + c1.y, 0.f);
    float pe = warp_red_sum(cx * v2.x + cy * v2.y);

    if (lane == 0) {
        out[(size_t)w * 2 + 0] = pr + rb2[0];
        out[(size_t)w * 2 + 1] = pe + eb2[0];
    }
}

// ---------------- launch ------------------------------------------------------
extern "C" void kernel_launch(void* const* d_in, const int* in_sizes, int n_in,
                              void* d_out, int out_size) {
    const float* x       = (const float*)d_in[0];
    const int*   ei      = (const int*)  d_in[1];
    const float* ln_in_g = (const float*)d_in[2];
    const float* ln_in_b = (const float*)d_in[3];
    const float* w_l1    = (const float*)d_in[4];
    const float* w_r1    = (const float*)d_in[5];
    const float* att1    = (const float*)d_in[6];
    const float* ln1_g   = (const float*)d_in[7];
    const float* ln1_b   = (const float*)d_in[8];
    const float* w_l2    = (const float*)d_in[9];
    const float* w_r2    = (const float*)d_in[10];
    const float* att2    = (const float*)d_in[11];
    const float* ln2_g   = (const float*)d_in[12];
    const float* ln2_b   = (const float*)d_in[13];
    const float* w_l3    = (const float*)d_in[14];
    const float* w_r3    = (const float*)d_in[15];
    const float* att3    = (const float*)d_in[16];
    const float* ln3_g   = (const float*)d_in[17];
    const float* ln3_b   = (const float*)d_in[18];
    const float* rtt_w1  = (const float*)d_in[19];
    const float* rtt_b1  = (const float*)d_in[20];
    const float* rtt_w2  = (const float*)d_in[21];
    const float* rtt_b2  = (const float*)d_in[22];
    const float* ret_w1  = (const float*)d_in[23];
    const float* ret_b1  = (const float*)d_in[24];
    const float* ret_w2  = (const float*)d_in[25];
    const float* ret_b2  = (const float*)d_in[26];
    float* out = (float*)d_out;

    __nv_bfloat16 *hh, *hl, *wh, *wl;
    float *xl, *xr;
    int *deg, *off, *cur, *csr;
    cudaGetSymbolAddress((void**)&hh,  g_hh);
    cudaGetSymbolAddress((void**)&hl,  g_hl);
    cudaGetSymbolAddress((void**)&wh,  g_wh);
    cudaGetSymbolAddress((void**)&wl,  g_wl);
    cudaGetSymbolAddress((void**)&xl,  g_xl);
    cudaGetSymbolAddress((void**)&xr,  g_xr);
    cudaGetSymbolAddress((void**)&deg, g_deg);
    cudaGetSymbolAddress((void**)&off, g_off);
    cudaGetSymbolAddress((void**)&cur, g_cur);
    cudaGetSymbolAddress((void**)&csr, g_csr);

    const int SMEM128 = (4 * 5120 + 4 * 4352) * 2;   // 75776 B
    const int SMEM64  = (4 * 5120 + 4 * 2304) * 2;   // 59392 B
    cudaFuncSetAttribute(gemm_bf16_kernel<128>,
                         cudaFuncAttributeMaxDynamicSharedMemorySize, SMEM128);
    cudaFuncSetAttribute(gemm_bf16_kernel<64>,
                         cudaFuncAttributeMaxDynamicSharedMemorySize, SMEM64);

    const int TB = 256;
    const int GTB = 128;
    int nodeBlocks  = (NN * 32 + TB - 1) / TB;
    int gatBlocks   = (NN * 32 + GTB - 1) / GTB;
    int nBlocksN    = (NN + TB - 1) / TB;
    int nBlocksE    = (ETT + TB - 1) / TB;
    dim3 gGemm(MPAD / 128, 2);

    WSrcs ws;
    ws.p[0] = w_l1; ws.p[1] = w_r1; ws.p[2] = w_l2; ws.p[3] = w_r2;
    ws.p[4] = w_l3; ws.p[5] = w_r3; ws.p[6] = rtt_w1; ws.p[7] = ret_w1;

    // launch order keeps gemm L0 at my-index 3 (= profiled launch).
    split_w_all_kernel<<<(WTOT + TB - 1) / TB, TB>>>(ws, wh, wl);            // 0
    ln_in_kernel<<<nodeBlocks, TB>>>(x, ln_in_g, ln_in_b, hh, hl);           // 1
    zero_int_kernel<<<nBlocksN, TB>>>(deg, NN);                              // 2
    gemm_bf16_kernel<128><<<gGemm, TB, SMEM128>>>(hh, hl, wh, wl,            // 3
                                                  OFF_WL1, OFF_WR1, xl, xr, 64, 128);

    // CSR build (graph shared by all 3 layers)
    degree_kernel<<<nBlocksE, TB>>>(ei, deg);
    scan_kernel<<<1, 1024>>>(deg, off, cur, NN);
    scatter_kernel<<<nBlocksE, TB>>>(ei, cur, csr);

    // layer 0 tail: fused GAT+LN (no residual, relu)
    gat_ln_kernel<4><<<gatBlocks, GTB>>>(xl, xr, att1, off, csr, hh, hl,
                                         ln1_g, ln1_b, 0.0f, 1);

    // layer 1: 128 -> 128, 4 heads, residual 0.1, relu
    gemm_bf16_kernel<128><<<gGemm, TB, SMEM128>>>(hh, hl, wh, wl,
                                                  OFF_WL2, OFF_WR2, xl, xr, 128, 128);
    gat_ln_kernel<4><<<gatBlocks, GTB>>>(xl, xr, att2, off, csr, hh, hl,
                                         ln2_g, ln2_b, 0.1f, 1);

    // layer 2: 128 -> 128, 1 head, residual 0.1, no relu
    gemm_bf16_kernel<128><<<gGemm, TB, SMEM128>>>(hh, hl, wh, wl,
                                                  OFF_WL3, OFF_WR3, xl, xr, 128, 128);
    gat_ln_kernel<1><<<gatBlocks, GTB>>>(xl, xr, att3, off, csr, hh, hl,
                                         ln3_g, ln3_b, 0.1f, 0);

    // prediction heads
    gemm_bf16_kernel<64><<<gGemm, TB, SMEM64>>>(hh, hl, wh, wl,
                                                OFF_RTT, OFF_RET, xl, xr, 128, 64);
    head_kernel<<<nodeBlocks, TB>>>(xl, xr, rtt_b1, rtt_w2, rtt_b2,
                                    ret_b1, ret_w2, ret_b2, out);
}

// round 15
// speedup vs baseline: 1.4464x; 1.4464x over previous
#include <cuda_runtime.h>
#include <cuda_bf16.h>
#include <cstdint>

#define NN  100000
#define MPAD 100096          // 782 * 128
#define EE  800000
#define ETT 900000           // EE + NN self loops
#define FIN 64
#define HIDD 128

// weight hi/lo buffer offsets (elements)
#define OFF_WL1 0
#define OFF_WR1 8192
#define OFF_WL2 16384
#define OFF_WR2 32768
#define OFF_WL3 49152
#define OFF_WR3 65536
#define OFF_RTT 81920
#define OFF_RET 90112
#define WTOT    98304

// ---------------- scratch (static device globals; no runtime alloc) ----------
__device__ __nv_bfloat16 g_hh[(size_t)MPAD * HIDD];
__device__ __nv_bfloat16 g_hl[(size_t)MPAD * HIDD];
__device__ __nv_bfloat16 g_wh[WTOT];
__device__ __nv_bfloat16 g_wl[WTOT];
__device__ float g_xl[(size_t)MPAD * HIDD];
__device__ float g_xr[(size_t)MPAD * HIDD];
__device__ int   g_deg[NN];
__device__ int   g_off[NN + 1];
__device__ int   g_cur[NN];
__device__ int   g_csr[ETT];

// ---------------- helpers ----------------------------------------------------
__device__ __forceinline__ uint32_t smem_u32(const void* p) {
    uint32_t a;
    asm("{ .reg .u64 t; cvta.to.shared.u64 t, %1; cvt.u32.u64 %0, t; }" : "=r"(a) : "l"(p));
    return a;
}
__device__ __forceinline__ float warp_red_sum(float v) {
#pragma unroll
    for (int d = 16; d > 0; d >>= 1) v += __shfl_xor_sync(0xFFFFFFFFu, v, d);
    return v;
}
__device__ __forceinline__ void cp16(uint32_t dst, const void* src) {
    asm volatile("cp.async.cg.shared.global [%0], [%1], 16;" :: "r"(dst), "l"(src));
}
#define CP_COMMIT() asm volatile("cp.async.commit_group;" ::: "memory")
#define CP_WAIT1()  asm volatile("cp.async.wait_group 1;" ::: "memory")

__device__ __forceinline__ void ldsm_x4(uint32_t* r, uint32_t addr) {
    asm volatile("ldmatrix.sync.aligned.m8n8.x4.shared.b16 {%0,%1,%2,%3}, [%4];"
                 : "=r"(r[0]), "=r"(r[1]), "=r"(r[2]), "=r"(r[3]) : "r"(addr));
}
__device__ __forceinline__ void ldsm_x4_t(uint32_t* r, uint32_t addr) {
    asm volatile("ldmatrix.sync.aligned.m8n8.x4.trans.shared.b16 {%0,%1,%2,%3}, [%4];"
                 : "=r"(r[0]), "=r"(r[1]), "=r"(r[2]), "=r"(r[3]) : "r"(addr));
}
__device__ __forceinline__ void mma_bf16(float* c, const uint32_t* a, const uint32_t* b) {
    asm volatile(
        "mma.sync.aligned.m16n8k16.row.col.f32.bf16.bf16.f32 "
        "{%0,%1,%2,%3}, {%4,%5,%6,%7}, {%8,%9}, {%0,%1,%2,%3};"
        : "+f"(c[0]), "+f"(c[1]), "+f"(c[2]), "+f"(c[3])
        : "r"(a[0]), "r"(a[1]), "r"(a[2]), "r"(a[3]), "r"(b[0]), "r"(b[1]));
}
__device__ __forceinline__ void bf16_split(float v, __nv_bfloat16& h, __nv_bfloat16& l) {
    h = __float2bfloat16_rn(v);
    l = __float2bfloat16_rn(v - __bfloat162float(h));
}

// ---------------- fused weight pre-split (single launch, 8 segments) ----------
struct WSrcs { const float* p[8]; };
__global__ void split_w_all_kernel(WSrcs srcs,
                                   __nv_bfloat16* __restrict__ dh,
                                   __nv_bfloat16* __restrict__ dl) {
    int i = blockIdx.x * blockDim.x + threadIdx.x;
    if (i >= WTOT) return;
    int seg, base;
    if      (i < 8192)  { seg = 0; base = 0; }
    else if (i < 16384) { seg = 1; base = 8192; }
    else if (i < 32768) { seg = 2; base = 16384; }
    else if (i < 49152) { seg = 3; base = 32768; }
    else if (i < 65536) { seg = 4; base = 49152; }
    else if (i < 81920) { seg = 5; base = 65536; }
    else if (i < 90112) { seg = 6; base = 81920; }
    else                { seg = 7; base = 90112; }
    float v = srcs.p[seg][i - base];
    __nv_bfloat16 h, l;
    bf16_split(v, h, l);
    dh[i] = h; dl[i] = l;
}

// ---------------- bf16 split-precision tensor-core GEMM (2-stage pipeline) ----
// B fragments via ldmatrix.x4.trans over n-tile PAIRS (half the smem ops).
template <int BN>
__global__ __launch_bounds__(256)
void gemm_bf16_kernel(const __nv_bfloat16* __restrict__ Ah,
                      const __nv_bfloat16* __restrict__ Al,
                      const __nv_bfloat16* __restrict__ Wh,
                      const __nv_bfloat16* __restrict__ Wl,
                      int woff0, int woff1,
                      float* __restrict__ C0, float* __restrict__ C1,
                      int K, int cstride) {
    constexpr int BM = 128, BK = 32;
    constexpr int AST = 40;
    constexpr int BST = BN + 8;
    constexpr int WN = BN / 2;
    constexpr int NT = WN / 8;
    constexpr int NP = NT / 2;           // n-tile pairs per warp
    constexpr int SZA = BM * AST;
    constexpr int SZB = BK * BST;

    extern __shared__ __nv_bfloat16 smem[];
    uint32_t base  = smem_u32(smem);
    uint32_t pAh   = base;
    uint32_t pAl   = base + 2u * SZA * 2u;
    uint32_t pBh   = base + 4u * SZA * 2u;
    uint32_t pBl   = pBh + 2u * SZB * 2u;

    const __nv_bfloat16* W_h = Wh + (blockIdx.y ? woff1 : woff0);
    const __nv_bfloat16* W_l = Wl + (blockIdx.y ? woff1 : woff0);
    float* C = blockIdx.y ? C1 : C0;
    int bm = blockIdx.x * BM;
    int tid = threadIdx.x, wid = tid >> 5, lane = tid & 31;
    int wm = wid >> 1, wn = wid & 1;

    float acc[2][NT][4];
#pragma unroll
    for (int i = 0; i < 2; i++)
#pragma unroll
        for (int j = 0; j < NT; j++)
#pragma unroll
            for (int q = 0; q < 4; q++) acc[i][j][q] = 0.0f;

    // A ldmatrix lane mapping (x4, non-trans)
    int a_tile = lane >> 3, a_r = lane & 7;
    int a_row_off = (a_tile & 1) * 8 + a_r;
    int a_k_off   = (a_tile >> 1) * 8;
    // B ldmatrix lane mapping (x4, trans)
    int b_row = ((lane >> 3) & 1) * 8 + (lane & 7);
    int b_colq = (lane >> 4) * 8;

    int nchunks = K / BK;

    auto load_stage = [&](int st, int k0) {
        uint32_t aoffs = (uint32_t)st * SZA * 2u;
        uint32_t boffs = (uint32_t)st * SZB * 2u;
        {
            int jj = tid * 2;
#pragma unroll
            for (int q = 0; q < 2; q++) {
                int j = jj + q, row = j >> 2, seg = j & 3;
                size_t so = (size_t)(bm + row) * K + k0 + seg * 8;
                uint32_t dofs = (uint32_t)(row * AST + seg * 8) * 2;
                cp16(pAh + aoffs + dofs, Ah + so);
                cp16(pAl + aoffs + dofs, Al + so);
            }
        }
        if (BN == 128) {
            int jj = tid * 2;
#pragma unroll
            for (int q = 0; q < 2; q++) {
                int j = jj + q, row = j >> 4, seg = j & 15;
                size_t so = (size_t)(k0 + row) * BN + seg * 8;
                uint32_t dofs = (uint32_t)(row * BST + seg * 8) * 2;
                cp16(pBh + boffs + dofs, W_h + so);
                cp16(pBl + boffs + dofs, W_l + so);
            }
        } else {
            int row = tid >> 3, seg = tid & 7;
            size_t so = (size_t)(k0 + row) * BN + seg * 8;
            uint32_t dofs = (uint32_t)(row * BST + seg * 8) * 2;
            cp16(pBh + boffs + dofs, W_h + so);
            cp16(pBl + boffs + dofs, W_l + so);
        }
    };

    load_stage(0, 0);
    CP_COMMIT();

    for (int c = 0; c < nchunks; c++) {
        if (c + 1 < nchunks) load_stage((c + 1) & 1, (c + 1) * BK);
        CP_COMMIT();
        CP_WAIT1();
        __syncthreads();

        uint32_t cAh = pAh + (uint32_t)(c & 1) * SZA * 2u;
        uint32_t cAl = pAl + (uint32_t)(c & 1) * SZA * 2u;
        uint32_t cBh = pBh + (uint32_t)(c & 1) * SZB * 2u;
        uint32_t cBl = pBl + (uint32_t)(c & 1) * SZB * 2u;

#pragma unroll
        for (int kk = 0; kk < 2; kk++) {
            uint32_t ah[2][4], al[2][4];
#pragma unroll
            for (int mt = 0; mt < 2; mt++) {
                int row = wm * 32 + mt * 16 + a_row_off;
                int kc  = kk * 16 + a_k_off;
                ldsm_x4(ah[mt], cAh + (uint32_t)(row * AST + kc) * 2);
                ldsm_x4(al[mt], cAl + (uint32_t)(row * AST + kc) * 2);
            }
#pragma unroll
            for (int p = 0; p < NP; p++) {
                int krow = kk * 16 + b_row;
                int ncol = wn * WN + p * 16 + b_colq;
                uint32_t bh[4], bl[4];
                ldsm_x4_t(bh, cBh + (uint32_t)(krow * BST + ncol) * 2);
                ldsm_x4_t(bl, cBl + (uint32_t)(krow * BST + ncol) * 2);
#pragma unroll
                for (int mt = 0; mt < 2; mt++) {
                    mma_bf16(acc[mt][2 * p],     ah[mt], bh);
                    mma_bf16(acc[mt][2 * p],     ah[mt], bl);
                    mma_bf16(acc[mt][2 * p],     al[mt], bh);
                    mma_bf16(acc[mt][2 * p + 1], ah[mt], bh + 2);
                    mma_bf16(acc[mt][2 * p + 1], ah[mt], bl + 2);
                    mma_bf16(acc[mt][2 * p + 1], al[mt], bh + 2);
                }
            }
        }
        __syncthreads();
    }

    int g = lane >> 2, tg = lane & 3;
#pragma unroll
    for (int mt = 0; mt < 2; mt++) {
#pragma unroll
        for (int nt = 0; nt < NT; nt++) {
            int row0 = bm + wm * 32 + mt * 16 + g;
            int col  = wn * WN + nt * 8 + tg * 2;
            *(float2*)(C + (size_t)row0 * cstride + col) =
                make_float2(acc[mt][nt][0], acc[mt][nt][1]);
            *(float2*)(C + (size_t)(row0 + 8) * cstride + col) =
                make_float2(acc[mt][nt][2], acc[mt][nt][3]);
        }
    }
}

// ---------------- CSR build ---------------------------------------------------
__global__ void zero_int_kernel(int* p, int n) {
    int i = blockIdx.x * blockDim.x + threadIdx.x;
    if (i < n) p[i] = 0;
}

__global__ void degree_kernel(const int* __restrict__ ei, int* __restrict__ deg) {
    int e = blockIdx.x * blockDim.x + threadIdx.x;
    if (e >= ETT) return;
    int dst = (e < EE) ? ei[EE + e] : (e - EE);
    atomicAdd(&deg[dst], 1);
}

__global__ void scan_kernel(const int* __restrict__ deg, int* __restrict__ off,
                            int* __restrict__ cur, int n) {
    __shared__ int wsum[32];
    __shared__ int carry_s;
    int tid = threadIdx.x, lane = tid & 31, wid = tid >> 5;
    if (tid == 0) carry_s = 0;
    __syncthreads();
    for (int base = 0; base < n; base += 4096) {
        int i4 = base + tid * 4;
        int4 v = make_int4(0, 0, 0, 0);
        if (i4 + 3 < n) v = *(const int4*)(deg + i4);
        else {
            if (i4 + 0 < n) v.x = deg[i4 + 0];
            if (i4 + 1 < n) v.y = deg[i4 + 1];
            if (i4 + 2 < n) v.z = deg[i4 + 2];
            if (i4 + 3 < n) v.w = deg[i4 + 3];
        }
        int t = v.x + v.y + v.z + v.w;
        int x = t;
#pragma unroll
        for (int d = 1; d < 32; d <<= 1) {
            int y = __shfl_up_sync(0xFFFFFFFFu, x, d);
            if (lane >= d) x += y;
        }
        if (lane == 31) wsum[wid] = x;
        __syncthreads();
        if (wid == 0) {
            int s = wsum[lane];
#pragma unroll
            for (int d = 1; d < 32; d <<= 1) {
                int y = __shfl_up_sync(0xFFFFFFFFu, s, d);
                if (lane >= d) s += y;
            }
            wsum[lane] = s;
        }
        __syncthreads();
        int pre = (wid > 0) ? wsum[wid - 1] : 0;
        int excl = carry_s + pre + (x - t);
        if (i4 < n) {
            int4 o;
            o.x = excl; o.y = o.x + v.x; o.z = o.y + v.y; o.w = o.z + v.z;
            if (i4 + 3 < n) { *(int4*)(off + i4) = o; *(int4*)(cur + i4) = o; }
            else {
                if (i4 + 0 < n) { off[i4 + 0] = o.x; cur[i4 + 0] = o.x; }
                if (i4 + 1 < n) { off[i4 + 1] = o.y; cur[i4 + 1] = o.y; }
                if (i4 + 2 < n) { off[i4 + 2] = o.z; cur[i4 + 2] = o.z; }
                if (i4 + 3 < n) { off[i4 + 3] = o.w; cur[i4 + 3] = o.w; }
            }
        }
        int btot = wsum[31];
        __syncthreads();
        if (tid == 0) carry_s += btot;
        __syncthreads();
    }
    if (tid == 0) off[n] = carry_s;
}

__global__ void scatter_kernel(const int* __restrict__ ei, int* __restrict__ cur,
                               int* __restrict__ csr) {
    int e = blockIdx.x * blockDim.x + threadIdx.x;
    if (e >= ETT) return;
    int src, dst;
    if (e < EE) { src = ei[e]; dst = ei[EE + e]; }
    else        { src = e - EE; dst = e - EE; }
    int pos = atomicAdd(&cur[dst], 1);
    csr[pos] = src;
}

// ---------------- LN on 64-dim input -> bf16 hi/lo (stride 64) ----------------
__global__ void ln_in_kernel(const float* __restrict__ x, const float* __restrict__ g,
                             const float* __restrict__ b,
                             __nv_bfloat16* __restrict__ hh,
                             __nv_bfloat16* __restrict__ hl) {
    int w = (blockIdx.x * blockDim.x + threadIdx.x) >> 5;
    if (w >= NN) return;
    int lane = threadIdx.x & 31;
    float2 v = *(const float2*)(x + (size_t)w * FIN + lane * 2);
    float s  = warp_red_sum(v.x + v.y);
    float sq = warp_red_sum(v.x * v.x + v.y * v.y);
    float mean = s * (1.0f / FIN);
    float var  = sq * (1.0f / FIN) - mean * mean;
    float rstd = rsqrtf(var + 1e-5f);
    float2 g2 = *(const float2*)(g + lane * 2);
    float2 b2 = *(const float2*)(b + lane * 2);
    float ox = (v.x - mean) * rstd * g2.x + b2.x;
    float oy = (v.y - mean) * rstd * g2.y + b2.y;
    __nv_bfloat16 hx, lx, hy, ly;
    bf16_split(ox, hx, lx);
    bf16_split(oy, hy, ly);
    *(__nv_bfloat162*)(hh + (size_t)w * FIN + lane * 2) = __nv_bfloat162(hx, hy);
    *(__nv_bfloat162*)(hl + (size_t)w * FIN + lane * 2) = __nv_bfloat162(lx, ly);
}

// ---------------- fused GATv2 (online softmax) + LN + residual + relu ---------
// 4x unrolled edge loop (MLP=4) — best measured config (R12).
template <int H>
__global__ void gat_ln_kernel(const float* __restrict__ xl, const float* __restrict__ xr,
                              const float* __restrict__ att,
                              const int* __restrict__ off, const int* __restrict__ csr,
                              __nv_bfloat16* __restrict__ hh,
                              __nv_bfloat16* __restrict__ hl,
                              const float* __restrict__ g, const float* __restrict__ b,
                              float rscale, int do_relu) {
    int w = (blockIdx.x * blockDim.x + threadIdx.x) >> 5;
    if (w >= NN) return;
    int lane = threadIdx.x & 31;
    const int G = 32 / H;

    float4 xr4 = *(const float4*)(xr + (size_t)w * HIDD + lane * 4);
    float4 at4 = *(const float4*)(att + lane * 4);
    int e0 = off[w], e1 = off[w + 1];

    float m = -1e30f, sum = 0.f;
    float4 acc = make_float4(0.f, 0.f, 0.f, 0.f);

    auto proc = [&](const float4& v) {
        float ex = v.x + xr4.x; ex = ex > 0.f ? ex : 0.2f * ex;
        float ey = v.y + xr4.y; ey = ey > 0.f ? ey : 0.2f * ey;
        float ez = v.z + xr4.z; ez = ez > 0.f ? ez : 0.2f * ez;
        float ew = v.w + xr4.w; ew = ew > 0.f ? ew : 0.2f * ew;
        float p = ex * at4.x + ey * at4.y + ez * at4.z + ew * at4.w;
#pragma unroll
        for (int d = 1; d < G; d <<= 1) p += __shfl_xor_sync(0xFFFFFFFFu, p, d);
        float nm = fmaxf(m, p);
        float sc = __expf(m - nm);
        float f  = __expf(p - nm);
        sum = sum * sc + f;
        acc.x = acc.x * sc + f * v.x;
        acc.y = acc.y * sc + f * v.y;
        acc.z = acc.z * sc + f * v.z;
        acc.w = acc.w * sc + f * v.w;
        m = nm;
    };

    int i = e0;
    for (; i + 4 <= e1; i += 4) {
        int s0 = csr[i], s1 = csr[i + 1], s2 = csr[i + 2], s3 = csr[i + 3];
        float4 v0 = *(const float4*)(xl + (size_t)s0 * HIDD + lane * 4);
        float4 v1 = *(const float4*)(xl + (size_t)s1 * HIDD + lane * 4);
        float4 v2 = *(const float4*)(xl + (size_t)s2 * HIDD + lane * 4);
        float4 v3 = *(const float4*)(xl + (size_t)s3 * HIDD + lane * 4);
        proc(v0); proc(v1); proc(v2); proc(v3);
    }
    for (; i < e1; i++) {
        int s = csr[i];
        float4 v = *(const float4*)(xl + (size_t)s * HIDD + lane * 4);
        proc(v);
    }

    float inv = 1.0f / sum;
    float4 o = make_float4(acc.x * inv, acc.y * inv, acc.z * inv, acc.w * inv);

    size_t idx = (size_t)w * HIDD + lane * 4;
    float s1r = warp_red_sum(o.x + o.y + o.z + o.w);
    float sqr = warp_red_sum(o.x * o.x + o.y * o.y + o.z * o.z + o.w * o.w);
    float mean = s1r * (1.0f / HIDD);
    float var  = sqr * (1.0f / HIDD) - mean * mean;
    float rstd = rsqrtf(var + 1e-5f);
    float4 g4 = *(const float4*)(g + lane * 4);
    float4 b4 = *(const float4*)(b + lane * 4);
    float4 y;
    y.x = (o.x - mean) * rstd * g4.x + b4.x;
    y.y = (o.y - mean) * rstd * g4.y + b4.y;
    y.z = (o.z - mean) * rstd * g4.z + b4.z;
    y.w = (o.w - mean) * rstd * g4.w + b4.w;
    if (rscale != 0.0f) {
        __nv_bfloat162 h01 = *(__nv_bfloat162*)(hh + idx);
        __nv_bfloat162 h23 = *(__nv_bfloat162*)(hh + idx + 2);
        __nv_bfloat162 l01 = *(__nv_bfloat162*)(hl + idx);
        __nv_bfloat162 l23 = *(__nv_bfloat162*)(hl + idx + 2);
        y.x += rscale * (__bfloat162float(h01.x) + __bfloat162float(l01.x));
        y.y += rscale * (__bfloat162float(h01.y) + __bfloat162float(l01.y));
        y.z += rscale * (__bfloat162float(h23.x) + __bfloat162float(l23.x));
        y.w += rscale * (__bfloat162float(h23.y) + __bfloat162float(l23.y));
    }
    if (do_relu) {
        y.x = fmaxf(y.x, 0.f); y.y = fmaxf(y.y, 0.f);
        y.z = fmaxf(y.z, 0.f); y.w = fmaxf(y.w, 0.f);
    }
    __nv_bfloat16 hx, lx, hy, ly, hz, lz, hw, lw;
    bf16_split(y.x, hx, lx); bf16_split(y.y, hy, ly);
    bf16_split(y.z, hz, lz); bf16_split(y.w, hw, lw);
    *(__nv_bfloat162*)(hh + idx)     = __nv_bfloat162(hx, hy);
    *(__nv_bfloat162*)(hh + idx + 2) = __nv_bfloat162(hz, hw);
    *(__nv_bfloat162*)(hl + idx)     = __nv_bfloat162(lx, ly);
    *(__nv_bfloat162*)(hl + idx + 2) = __nv_bfloat162(lz, lw);
}

// ---------------- prediction heads epilogue -----------------------------------
__global__ void head_kernel(const float* __restrict__ hr, const float* __restrict__ he,
                            const float* __restrict__ rb1, const float* __restrict__ rw2,
                            const float* __restrict__ rb2,
                            const float* __restrict__ eb1, const float* __restrict__ ew2,
                            const float* __restrict__ eb2,
                            float* __restrict__ out) {
    int w = (blockIdx.x * blockDim.x + threadIdx.x) >> 5;
    if (w >= NN) return;
    int lane = threadIdx.x & 31;

    float2 a  = *(const float2*)(hr + (size_t)w * 64 + lane * 2);
    float2 b1 = *(const float2*)(rb1 + lane * 2);
    float2 w2 = *(const float2*)(rw2 + lane * 2);
    float ax = fmaxf(a.x + b1.x, 0.f), ay = fmaxf(a.y + b1.y, 0.f);
    float pr = warp_red_sum(ax * w2.x + ay * w2.y);

    float2 c  = *(const float2*)(he + (size_t)w * 64 + lane * 2);
    float2 c1 = *(const float2*)(eb1 + lane * 2);
    float2 v2 = *(const float2*)(ew2 + lane * 2);
    float cx = fmaxf(c.x + c1.x, 0.f), cy = fmaxf(c.y + c1.y, 0.f);
    float pe = warp_red_sum(cx * v2.x + cy * v2.y);

    if (lane == 0) {
        out[(size_t)w * 2 + 0] = pr + rb2[0];
        out[(size_t)w * 2 + 1] = pe + eb2[0];
    }
}

// ---------------- launch ------------------------------------------------------
extern "C" void kernel_launch(void* const* d_in, const int* in_sizes, int n_in,
                              void* d_out, int out_size) {
    const float* x       = (const float*)d_in[0];
    const int*   ei      = (const int*)  d_in[1];
    const float* ln_in_g = (const float*)d_in[2];
    const float* ln_in_b = (const float*)d_in[3];
    const float* w_l1    = (const float*)d_in[4];
    const float* w_r1    = (const float*)d_in[5];
    const float* att1    = (const float*)d_in[6];
    const float* ln1_g   = (const float*)d_in[7];
    const float* ln1_b   = (const float*)d_in[8];
    const float* w_l2    = (const float*)d_in[9];
    const float* w_r2    = (const float*)d_in[10];
    const float* att2    = (const float*)d_in[11];
    const float* ln2_g   = (const float*)d_in[12];
    const float* ln2_b   = (const float*)d_in[13];
    const float* w_l3    = (const float*)d_in[14];
    const float* w_r3    = (const float*)d_in[15];
    const float* att3    = (const float*)d_in[16];
    const float* ln3_g   = (const float*)d_in[17];
    const float* ln3_b   = (const float*)d_in[18];
    const float* rtt_w1  = (const float*)d_in[19];
    const float* rtt_b1  = (const float*)d_in[20];
    const float* rtt_w2  = (const float*)d_in[21];
    const float* rtt_b2  = (const float*)d_in[22];
    const float* ret_w1  = (const float*)d_in[23];
    const float* ret_b1  = (const float*)d_in[24];
    const float* ret_w2  = (const float*)d_in[25];
    const float* ret_b2  = (const float*)d_in[26];
    float* out = (float*)d_out;

    __nv_bfloat16 *hh, *hl, *wh, *wl;
    float *xl, *xr;
    int *deg, *off, *cur, *csr;
    cudaGetSymbolAddress((void**)&hh,  g_hh);
    cudaGetSymbolAddress((void**)&hl,  g_hl);
    cudaGetSymbolAddress((void**)&wh,  g_wh);
    cudaGetSymbolAddress((void**)&wl,  g_wl);
    cudaGetSymbolAddress((void**)&xl,  g_xl);
    cudaGetSymbolAddress((void**)&xr,  g_xr);
    cudaGetSymbolAddress((void**)&deg, g_deg);
    cudaGetSymbolAddress((void**)&off, g_off);
    cudaGetSymbolAddress((void**)&cur, g_cur);
    cudaGetSymbolAddress((void**)&csr, g_csr);

    const int SMEM128 = (4 * 5120 + 4 * 4352) * 2;   // 75776 B
    const int SMEM64  = (4 * 5120 + 4 * 2304) * 2;   // 59392 B
    cudaFuncSetAttribute(gemm_bf16_kernel<128>,
                         cudaFuncAttributeMaxDynamicSharedMemorySize, SMEM128);
    cudaFuncSetAttribute(gemm_bf16_kernel<64>,
                         cudaFuncAttributeMaxDynamicSharedMemorySize, SMEM64);

    const int TB = 256;
    const int GTB = 128;
    int nodeBlocks  = (NN * 32 + TB - 1) / TB;
    int gatBlocks   = (NN * 32 + GTB - 1) / GTB;
    int nBlocksN    = (NN + TB - 1) / TB;
    int nBlocksE    = (ETT + TB - 1) / TB;
    dim3 gGemm(MPAD / 128, 2);

    WSrcs ws;
    ws.p[0] = w_l1; ws.p[1] = w_r1; ws.p[2] = w_l2; ws.p[3] = w_r2;
    ws.p[4] = w_l3; ws.p[5] = w_r3; ws.p[6] = rtt_w1; ws.p[7] = ret_w1;

    // launch order keeps gemm L0 at my-index 3 (= profiled launch).
    split_w_all_kernel<<<(WTOT + TB - 1) / TB, TB>>>(ws, wh, wl);            // 0
    ln_in_kernel<<<nodeBlocks, TB>>>(x, ln_in_g, ln_in_b, hh, hl);           // 1
    zero_int_kernel<<<nBlocksN, TB>>>(deg, NN);                              // 2
    gemm_bf16_kernel<128><<<gGemm, TB, SMEM128>>>(hh, hl, wh, wl,            // 3
                                                  OFF_WL1, OFF_WR1, xl, xr, 64, 128);

    // CSR build (graph shared by all 3 layers)
    degree_kernel<<<nBlocksE, TB>>>(ei, deg);
    scan_kernel<<<1, 1024>>>(deg, off, cur, NN);
    scatter_kernel<<<nBlocksE, TB>>>(ei, cur, csr);

    // layer 0 tail: fused GAT+LN (no residual, relu)
    gat_ln_kernel<4><<<gatBlocks, GTB>>>(xl, xr, att1, off, csr, hh, hl,
                                         ln1_g, ln1_b, 0.0f, 1);

    // layer 1: 128 -> 128, 4 heads, residual 0.1, relu
    gemm_bf16_kernel<128><<<gGemm, TB, SMEM128>>>(hh, hl, wh, wl,
                                                  OFF_WL2, OFF_WR2, xl, xr, 128, 128);
    gat_ln_kernel<4><<<gatBlocks, GTB>>>(xl, xr, att2, off, csr, hh, hl,
                                         ln2_g, ln2_b, 0.1f, 1);

    // layer 2: 128 -> 128, 1 head, residual 0.1, no relu
    gemm_bf16_kernel<128><<<gGemm, TB, SMEM128>>>(hh, hl, wh, wl,
                                                  OFF_WL3, OFF_WR3, xl, xr, 128, 128);
    gat_ln_kernel<1><<<gatBlocks, GTB>>>(xl, xr, att3, off, csr, hh, hl,
                                         ln3_g, ln3_b, 0.1f, 0);

    // prediction heads
    gemm_bf16_kernel<64><<<gGemm, TB, SMEM64>>>(hh, hl, wh, wl,
                                                OFF_RTT, OFF_RET, xl, xr, 128, 64);
    head_kernel<<<nodeBlocks, TB>>>(xl, xr, rtt_b1, rtt_w2, rtt_b2,
                                    ret_b1, ret_w2, ret_b2, out);
}

// round 16
// speedup vs baseline: 1.4598x; 1.0092x over previous
#include <cuda_runtime.h>
#include <cuda_bf16.h>
#include <cstdint>

#define NN  100000
#define MPAD 100096          // 782 * 128
#define EE  800000
#define ETT 900000           // EE + NN self loops
#define FIN 64
#define HIDD 128

// weight hi/lo buffer offsets (elements)
#define OFF_WL1 0
#define OFF_WR1 8192
#define OFF_WL2 16384
#define OFF_WR2 32768
#define OFF_WL3 49152
#define OFF_WR3 65536
#define OFF_RTT 81920
#define OFF_RET 90112
#define WTOT    98304

// ---------------- scratch (static device globals; no runtime alloc) ----------
__device__ __nv_bfloat16 g_hh[(size_t)MPAD * HIDD];
__device__ __nv_bfloat16 g_hl[(size_t)MPAD * HIDD];
__device__ __nv_bfloat16 g_wh[WTOT];
__device__ __nv_bfloat16 g_wl[WTOT];
__device__ float g_xl[(size_t)MPAD * HIDD];
__device__ float g_xr[(size_t)MPAD * HIDD];
__device__ int   g_deg[NN];
__device__ int   g_off[NN + 1];
__device__ int   g_cur[NN];
__device__ int   g_csr[ETT];

// ---------------- helpers ----------------------------------------------------
__device__ __forceinline__ uint32_t smem_u32(const void* p) {
    uint32_t a;
    asm("{ .reg .u64 t; cvta.to.shared.u64 t, %1; cvt.u32.u64 %0, t; }" : "=r"(a) : "l"(p));
    return a;
}
__device__ __forceinline__ float warp_red_sum(float v) {
#pragma unroll
    for (int d = 16; d > 0; d >>= 1) v += __shfl_xor_sync(0xFFFFFFFFu, v, d);
    return v;
}
__device__ __forceinline__ void cp16(uint32_t dst, const void* src) {
    asm volatile("cp.async.cg.shared.global [%0], [%1], 16;" :: "r"(dst), "l"(src));
}
#define CP_COMMIT() asm volatile("cp.async.commit_group;" ::: "memory")
#define CP_WAIT1()  asm volatile("cp.async.wait_group 1;" ::: "memory")

__device__ __forceinline__ void ldsm_x4(uint32_t* r, uint32_t addr) {
    asm volatile("ldmatrix.sync.aligned.m8n8.x4.shared.b16 {%0,%1,%2,%3}, [%4];"
                 : "=r"(r[0]), "=r"(r[1]), "=r"(r[2]), "=r"(r[3]) : "r"(addr));
}
__device__ __forceinline__ void ldsm_x4_t(uint32_t* r, uint32_t addr) {
    asm volatile("ldmatrix.sync.aligned.m8n8.x4.trans.shared.b16 {%0,%1,%2,%3}, [%4];"
                 : "=r"(r[0]), "=r"(r[1]), "=r"(r[2]), "=r"(r[3]) : "r"(addr));
}
__device__ __forceinline__ void mma_bf16(float* c, const uint32_t* a, const uint32_t* b) {
    asm volatile(
        "mma.sync.aligned.m16n8k16.row.col.f32.bf16.bf16.f32 "
        "{%0,%1,%2,%3}, {%4,%5,%6,%7}, {%8,%9}, {%0,%1,%2,%3};"
        : "+f"(c[0]), "+f"(c[1]), "+f"(c[2]), "+f"(c[3])
        : "r"(a[0]), "r"(a[1]), "r"(a[2]), "r"(a[3]), "r"(b[0]), "r"(b[1]));
}
__device__ __forceinline__ void bf16_split(float v, __nv_bfloat16& h, __nv_bfloat16& l) {
    h = __float2bfloat16_rn(v);
    l = __float2bfloat16_rn(v - __bfloat162float(h));
}

// ---------------- fused weight pre-split (single launch, 8 segments) ----------
struct WSrcs { const float* p[8]; };
__global__ void split_w_all_kernel(WSrcs srcs,
                                   __nv_bfloat16* __restrict__ dh,
                                   __nv_bfloat16* __restrict__ dl) {
    int i = blockIdx.x * blockDim.x + threadIdx.x;
    if (i >= WTOT) return;
    int seg, base;
    if      (i < 8192)  { seg = 0; base = 0; }
    else if (i < 16384) { seg = 1; base = 8192; }
    else if (i < 32768) { seg = 2; base = 16384; }
    else if (i < 49152) { seg = 3; base = 32768; }
    else if (i < 65536) { seg = 4; base = 49152; }
    else if (i < 81920) { seg = 5; base = 65536; }
    else if (i < 90112) { seg = 6; base = 81920; }
    else                { seg = 7; base = 90112; }
    float v = srcs.p[seg][i - base];
    __nv_bfloat16 h, l;
    bf16_split(v, h, l);
    dh[i] = h; dl[i] = l;
}

// ---------------- bf16 split-precision tensor-core GEMM (2-stage pipeline) ----
// B fragments via ldmatrix.x4.trans; MMAs issued TERM-MAJOR so consecutive
// same-accumulator HMMAs are separated by 3 independent ones (latency hiding).
// Per-accumulator accumulation order unchanged -> bit-identical results.
template <int BN>
__global__ __launch_bounds__(256)
void gemm_bf16_kernel(const __nv_bfloat16* __restrict__ Ah,
                      const __nv_bfloat16* __restrict__ Al,
                      const __nv_bfloat16* __restrict__ Wh,
                      const __nv_bfloat16* __restrict__ Wl,
                      int woff0, int woff1,
                      float* __restrict__ C0, float* __restrict__ C1,
                      int K, int cstride) {
    constexpr int BM = 128, BK = 32;
    constexpr int AST = 40;
    constexpr int BST = BN + 8;
    constexpr int WN = BN / 2;
    constexpr int NT = WN / 8;
    constexpr int NP = NT / 2;           // n-tile pairs per warp
    constexpr int SZA = BM * AST;
    constexpr int SZB = BK * BST;

    extern __shared__ __nv_bfloat16 smem[];
    uint32_t base  = smem_u32(smem);
    uint32_t pAh   = base;
    uint32_t pAl   = base + 2u * SZA * 2u;
    uint32_t pBh   = base + 4u * SZA * 2u;
    uint32_t pBl   = pBh + 2u * SZB * 2u;

    const __nv_bfloat16* W_h = Wh + (blockIdx.y ? woff1 : woff0);
    const __nv_bfloat16* W_l = Wl + (blockIdx.y ? woff1 : woff0);
    float* C = blockIdx.y ? C1 : C0;
    int bm = blockIdx.x * BM;
    int tid = threadIdx.x, wid = tid >> 5, lane = tid & 31;
    int wm = wid >> 1, wn = wid & 1;

    float acc[2][NT][4];
#pragma unroll
    for (int i = 0; i < 2; i++)
#pragma unroll
        for (int j = 0; j < NT; j++)
#pragma unroll
            for (int q = 0; q < 4; q++) acc[i][j][q] = 0.0f;

    // A ldmatrix lane mapping (x4, non-trans)
    int a_tile = lane >> 3, a_r = lane & 7;
    int a_row_off = (a_tile & 1) * 8 + a_r;
    int a_k_off   = (a_tile >> 1) * 8;
    // B ldmatrix lane mapping (x4, trans)
    int b_row = ((lane >> 3) & 1) * 8 + (lane & 7);
    int b_colq = (lane >> 4) * 8;

    int nchunks = K / BK;

    auto load_stage = [&](int st, int k0) {
        uint32_t aoffs = (uint32_t)st * SZA * 2u;
        uint32_t boffs = (uint32_t)st * SZB * 2u;
        {
            int jj = tid * 2;
#pragma unroll
            for (int q = 0; q < 2; q++) {
                int j = jj + q, row = j >> 2, seg = j & 3;
                size_t so = (size_t)(bm + row) * K + k0 + seg * 8;
                uint32_t dofs = (uint32_t)(row * AST + seg * 8) * 2;
                cp16(pAh + aoffs + dofs, Ah + so);
                cp16(pAl + aoffs + dofs, Al + so);
            }
        }
        if (BN == 128) {
            int jj = tid * 2;
#pragma unroll
            for (int q = 0; q < 2; q++) {
                int j = jj + q, row = j >> 4, seg = j & 15;
                size_t so = (size_t)(k0 + row) * BN + seg * 8;
                uint32_t dofs = (uint32_t)(row * BST + seg * 8) * 2;
                cp16(pBh + boffs + dofs, W_h + so);
                cp16(pBl + boffs + dofs, W_l + so);
            }
        } else {
            int row = tid >> 3, seg = tid & 7;
            size_t so = (size_t)(k0 + row) * BN + seg * 8;
            uint32_t dofs = (uint32_t)(row * BST + seg * 8) * 2;
            cp16(pBh + boffs + dofs, W_h + so);
            cp16(pBl + boffs + dofs, W_l + so);
        }
    };

    load_stage(0, 0);
    CP_COMMIT();

    for (int c = 0; c < nchunks; c++) {
        if (c + 1 < nchunks) load_stage((c + 1) & 1, (c + 1) * BK);
        CP_COMMIT();
        CP_WAIT1();
        __syncthreads();

        uint32_t cAh = pAh + (uint32_t)(c & 1) * SZA * 2u;
        uint32_t cAl = pAl + (uint32_t)(c & 1) * SZA * 2u;
        uint32_t cBh = pBh + (uint32_t)(c & 1) * SZB * 2u;
        uint32_t cBl = pBl + (uint32_t)(c & 1) * SZB * 2u;

#pragma unroll
        for (int kk = 0; kk < 2; kk++) {
            uint32_t ah[2][4], al[2][4];
#pragma unroll
            for (int mt = 0; mt < 2; mt++) {
                int row = wm * 32 + mt * 16 + a_row_off;
                int kc  = kk * 16 + a_k_off;
                ldsm_x4(ah[mt], cAh + (uint32_t)(row * AST + kc) * 2);
                ldsm_x4(al[mt], cAl + (uint32_t)(row * AST + kc) * 2);
            }
#pragma unroll
            for (int p = 0; p < NP; p++) {
                int krow = kk * 16 + b_row;
                int ncol = wn * WN + p * 16 + b_colq;
                uint32_t bh[4], bl[4];
                ldsm_x4_t(bh, cBh + (uint32_t)(krow * BST + ncol) * 2);
                ldsm_x4_t(bl, cBl + (uint32_t)(krow * BST + ncol) * 2);
                // term-major issue: 4 independent MMAs per term round.
                // per-acc order stays (ah*bh, ah*bl, al*bh) -> bit-identical.
#pragma unroll
                for (int mt = 0; mt < 2; mt++) {
                    mma_bf16(acc[mt][2 * p],     ah[mt], bh);
                    mma_bf16(acc[mt][2 * p + 1], ah[mt], bh + 2);
                }
#pragma unroll
                for (int mt = 0; mt < 2; mt++) {
                    mma_bf16(acc[mt][2 * p],     ah[mt], bl);
                    mma_bf16(acc[mt][2 * p + 1], ah[mt], bl + 2);
                }
#pragma unroll
                for (int mt = 0; mt < 2; mt++) {
                    mma_bf16(acc[mt][2 * p],     al[mt], bh);
                    mma_bf16(acc[mt][2 * p + 1], al[mt], bh + 2);
                }
            }
        }
        __syncthreads();
    }

    int g = lane >> 2, tg = lane & 3;
#pragma unroll
    for (int mt = 0; mt < 2; mt++) {
#pragma unroll
        for (int nt = 0; nt < NT; nt++) {
            int row0 = bm + wm * 32 + mt * 16 + g;
            int col  = wn * WN + nt * 8 + tg * 2;
            *(float2*)(C + (size_t)row0 * cstride + col) =
                make_float2(acc[mt][nt][0], acc[mt][nt][1]);
            *(float2*)(C + (size_t)(row0 + 8) * cstride + col) =
                make_float2(acc[mt][nt][2], acc[mt][nt][3]);
        }
    }
}

// ---------------- CSR build ---------------------------------------------------
__global__ void zero_int_kernel(int* p, int n) {
    int i = blockIdx.x * blockDim.x + threadIdx.x;
    if (i < n) p[i] = 0;
}

__global__ void degree_kernel(const int* __restrict__ ei, int* __restrict__ deg) {
    int e = blockIdx.x * blockDim.x + threadIdx.x;
    if (e >= ETT) return;
    int dst = (e < EE) ? ei[EE + e] : (e - EE);
    atomicAdd(&deg[dst], 1);
}

__global__ void scan_kernel(const int* __restrict__ deg, int* __restrict__ off,
                            int* __restrict__ cur, int n) {
    __shared__ int wsum[32];
    __shared__ int carry_s;
    int tid = threadIdx.x, lane = tid & 31, wid = tid >> 5;
    if (tid == 0) carry_s = 0;
    __syncthreads();
    for (int base = 0; base < n; base += 4096) {
        int i4 = base + tid * 4;
        int4 v = make_int4(0, 0, 0, 0);
        if (i4 + 3 < n) v = *(const int4*)(deg + i4);
        else {
            if (i4 + 0 < n) v.x = deg[i4 + 0];
            if (i4 + 1 < n) v.y = deg[i4 + 1];
            if (i4 + 2 < n) v.z = deg[i4 + 2];
            if (i4 + 3 < n) v.w = deg[i4 + 3];
        }
        int t = v.x + v.y + v.z + v.w;
        int x = t;
#pragma unroll
        for (int d = 1; d < 32; d <<= 1) {
            int y = __shfl_up_sync(0xFFFFFFFFu, x, d);
            if (lane >= d) x += y;
        }
        if (lane == 31) wsum[wid] = x;
        __syncthreads();
        if (wid == 0) {
            int s = wsum[lane];
#pragma unroll
            for (int d = 1; d < 32; d <<= 1) {
                int y = __shfl_up_sync(0xFFFFFFFFu, s, d);
                if (lane >= d) s += y;
            }
            wsum[lane] = s;
        }
        __syncthreads();
        int pre = (wid > 0) ? wsum[wid - 1] : 0;
        int excl = carry_s + pre + (x - t);
        if (i4 < n) {
            int4 o;
            o.x = excl; o.y = o.x + v.x; o.z = o.y + v.y; o.w = o.z + v.z;
            if (i4 + 3 < n) { *(int4*)(off + i4) = o; *(int4*)(cur + i4) = o; }
            else {
                if (i4 + 0 < n) { off[i4 + 0] = o.x; cur[i4 + 0] = o.x; }
                if (i4 + 1 < n) { off[i4 + 1] = o.y; cur[i4 + 1] = o.y; }
                if (i4 + 2 < n) { off[i4 + 2] = o.z; cur[i4 + 2] = o.z; }
                if (i4 + 3 < n) { off[i4 + 3] = o.w; cur[i4 + 3] = o.w; }
            }
        }
        int btot = wsum[31];
        __syncthreads();
        if (tid == 0) carry_s += btot;
        __syncthreads();
    }
    if (tid == 0) off[n] = carry_s;
}

__global__ void scatter_kernel(const int* __restrict__ ei, int* __restrict__ cur,
                               int* __restrict__ csr) {
    int e = blockIdx.x * blockDim.x + threadIdx.x;
    if (e >= ETT) return;
    int src, dst;
    if (e < EE) { src = ei[e]; dst = ei[EE + e]; }
    else        { src = e - EE; dst = e - EE; }
    int pos = atomicAdd(&cur[dst], 1);
    csr[pos] = src;
}

// ---------------- LN on 64-dim input -> bf16 hi/lo (stride 64) ----------------
__global__ void ln_in_kernel(const float* __restrict__ x, const float* __restrict__ g,
                             const float* __restrict__ b,
                             __nv_bfloat16* __restrict__ hh,
                             __nv_bfloat16* __restrict__ hl) {
    int w = (blockIdx.x * blockDim.x + threadIdx.x) >> 5;
    if (w >= NN) return;
    int lane = threadIdx.x & 31;
    float2 v = *(const float2*)(x + (size_t)w * FIN + lane * 2);
    float s  = warp_red_sum(v.x + v.y);
    float sq = warp_red_sum(v.x * v.x + v.y * v.y);
    float mean = s * (1.0f / FIN);
    float var  = sq * (1.0f / FIN) - mean * mean;
    float rstd = rsqrtf(var + 1e-5f);
    float2 g2 = *(const float2*)(g + lane * 2);
    float2 b2 = *(const float2*)(b + lane * 2);
    float ox = (v.x - mean) * rstd * g2.x + b2.x;
    float oy = (v.y - mean) * rstd * g2.y + b2.y;
    __nv_bfloat16 hx, lx, hy, ly;
    bf16_split(ox, hx, lx);
    bf16_split(oy, hy, ly);
    *(__nv_bfloat162*)(hh + (size_t)w * FIN + lane * 2) = __nv_bfloat162(hx, hy);
    *(__nv_bfloat162*)(hl + (size_t)w * FIN + lane * 2) = __nv_bfloat162(lx, ly);
}

// ---------------- fused GATv2 (online softmax) + LN + residual + relu ---------
// 4x unrolled edge loop (MLP=4) — best measured config (R12).
template <int H>
__global__ void gat_ln_kernel(const float* __restrict__ xl, const float* __restrict__ xr,
                              const float* __restrict__ att,
                              const int* __restrict__ off, const int* __restrict__ csr,
                              __nv_bfloat16* __restrict__ hh,
                              __nv_bfloat16* __restrict__ hl,
                              const float* __restrict__ g, const float* __restrict__ b,
                              float rscale, int do_relu) {
    int w = (blockIdx.x * blockDim.x + threadIdx.x) >> 5;
    if (w >= NN) return;
    int lane = threadIdx.x & 31;
    const int G = 32 / H;

    float4 xr4 = *(const float4*)(xr + (size_t)w * HIDD + lane * 4);
    float4 at4 = *(const float4*)(att + lane * 4);
    int e0 = off[w], e1 = off[w + 1];

    float m = -1e30f, sum = 0.f;
    float4 acc = make_float4(0.f, 0.f, 0.f, 0.f);

    auto proc = [&](const float4& v) {
        float ex = v.x + xr4.x; ex = ex > 0.f ? ex : 0.2f * ex;
        float ey = v.y + xr4.y; ey = ey > 0.f ? ey : 0.2f * ey;
        float ez = v.z + xr4.z; ez = ez > 0.f ? ez : 0.2f * ez;
        float ew = v.w + xr4.w; ew = ew > 0.f ? ew : 0.2f * ew;
        float p = ex * at4.x + ey * at4.y + ez * at4.z + ew * at4.w;
#pragma unroll
        for (int d = 1; d < G; d <<= 1) p += __shfl_xor_sync(0xFFFFFFFFu, p, d);
        float nm = fmaxf(m, p);
        float sc = __expf(m - nm);
        float f  = __expf(p - nm);
        sum = sum * sc + f;
        acc.x = acc.x * sc + f * v.x;
        acc.y = acc.y * sc + f * v.y;
        acc.z = acc.z * sc + f * v.z;
        acc.w = acc.w * sc + f * v.w;
        m = nm;
    };

    int i = e0;
    for (; i + 4 <= e1; i += 4) {
        int s0 = csr[i], s1 = csr[i + 1], s2 = csr[i + 2], s3 = csr[i + 3];
        float4 v0 = *(const float4*)(xl + (size_t)s0 * HIDD + lane * 4);
        float4 v1 = *(const float4*)(xl + (size_t)s1 * HIDD + lane * 4);
        float4 v2 = *(const float4*)(xl + (size_t)s2 * HIDD + lane * 4);
        float4 v3 = *(const float4*)(xl + (size_t)s3 * HIDD + lane * 4);
        proc(v0); proc(v1); proc(v2); proc(v3);
    }
    for (; i < e1; i++) {
        int s = csr[i];
        float4 v = *(const float4*)(xl + (size_t)s * HIDD + lane * 4);
        proc(v);
    }

    float inv = 1.0f / sum;
    float4 o = make_float4(acc.x * inv, acc.y * inv, acc.z * inv, acc.w * inv);

    size_t idx = (size_t)w * HIDD + lane * 4;
    float s1r = warp_red_sum(o.x + o.y + o.z + o.w);
    float sqr = warp_red_sum(o.x * o.x + o.y * o.y + o.z * o.z + o.w * o.w);
    float mean = s1r * (1.0f / HIDD);
    float var  = sqr * (1.0f / HIDD) - mean * mean;
    float rstd = rsqrtf(var + 1e-5f);
    float4 g4 = *(const float4*)(g + lane * 4);
    float4 b4 = *(const float4*)(b + lane * 4);
    float4 y;
    y.x = (o.x - mean) * rstd * g4.x + b4.x;
    y.y = (o.y - mean) * rstd * g4.y + b4.y;
    y.z = (o.z - mean) * rstd * g4.z + b4.z;
    y.w = (o.w - mean) * rstd * g4.w + b4.w;
    if (rscale != 0.0f) {
        __nv_bfloat162 h01 = *(__nv_bfloat162*)(hh + idx);
        __nv_bfloat162 h23 = *(__nv_bfloat162*)(hh + idx + 2);
        __nv_bfloat162 l01 = *(__nv_bfloat162*)(hl + idx);
        __nv_bfloat162 l23 = *(__nv_bfloat162*)(hl + idx + 2);
        y.x += rscale * (__bfloat162float(h01.x) + __bfloat162float(l01.x));
        y.y += rscale * (__bfloat162float(h01.y) + __bfloat162float(l01.y));
        y.z += rscale * (__bfloat162float(h23.x) + __bfloat162float(l23.x));
        y.w += rscale * (__bfloat162float(h23.y) + __bfloat162float(l23.y));
    }
    if (do_relu) {
        y.x = fmaxf(y.x, 0.f); y.y = fmaxf(y.y, 0.f);
        y.z = fmaxf(y.z, 0.f); y.w = fmaxf(y.w, 0.f);
    }
    __nv_bfloat16 hx, lx, hy, ly, hz, lz, hw, lw;
    bf16_split(y.x, hx, lx); bf16_split(y.y, hy, ly);
    bf16_split(y.z, hz, lz); bf16_split(y.w, hw, lw);
    *(__nv_bfloat162*)(hh + idx)     = __nv_bfloat162(hx, hy);
    *(__nv_bfloat162*)(hh + idx + 2) = __nv_bfloat162(hz, hw);
    *(__nv_bfloat162*)(hl + idx)     = __nv_bfloat162(lx, ly);
    *(__nv_bfloat162*)(hl + idx + 2) = __nv_bfloat162(lz, lw);
}

// ---------------- prediction heads epilogue -----------------------------------
__global__ void head_kernel(const float* __restrict__ hr, const float* __restrict__ he,
                            const float* __restrict__ rb1, const float* __restrict__ rw2,
                            const float* __restrict__ rb2,
                            const float* __restrict__ eb1, const float* __restrict__ ew2,
                            const float* __restrict__ eb2,
                            float* __restrict__ out) {
    int w = (blockIdx.x * blockDim.x + threadIdx.x) >> 5;
    if (w >= NN) return;
    int lane = threadIdx.x & 31;

    float2 a  = *(const float2*)(hr + (size_t)w * 64 + lane * 2);
    float2 b1 = *(const float2*)(rb1 + lane * 2);
    float2 w2 = *(const float2*)(rw2 + lane * 2);
    float ax = fmaxf(a.x + b1.x, 0.f), ay = fmaxf(a.y + b1.y, 0.f);
    float pr = warp_red_sum(ax * w2.x + ay * w2.y);

    float2 c  = *(const float2*)(he + (size_t)w * 64 + lane * 2);
    float2 c1 = *(const float2*)(eb1 + lane * 2);
    float2 v2 = *(const float2*)(ew2 + lane * 2);
    float cx = fmaxf(c.x + c1.x, 0.f), cy = fmaxf(c.y + c1.y, 0.f);
    float pe = warp_red_sum(cx * v2.x + cy * v2.y);

    if (lane == 0) {
        out[(size_t)w * 2 + 0] = pr + rb2[0];
        out[(size_t)w * 2 + 1] = pe + eb2[0];
    }
}

// ---------------- launch ------------------------------------------------------
extern "C" void kernel_launch(void* const* d_in, const int* in_sizes, int n_in,
                              void* d_out, int out_size) {
    const float* x       = (const float*)d_in[0];
    const int*   ei      = (const int*)  d_in[1];
    const float* ln_in_g = (const float*)d_in[2];
    const float* ln_in_b = (const float*)d_in[3];
    const float* w_l1    = (const float*)d_in[4];
    const float* w_r1    = (const float*)d_in[5];
    const float* att1    = (const float*)d_in[6];
    const float* ln1_g   = (const float*)d_in[7];
    const float* ln1_b   = (const float*)d_in[8];
    const float* w_l2    = (const float*)d_in[9];
    const float* w_r2    = (const float*)d_in[10];
    const float* att2    = (const float*)d_in[11];
    const float* ln2_g   = (const float*)d_in[12];
    const float* ln2_b   = (const float*)d_in[13];
    const float* w_l3    = (const float*)d_in[14];
    const float* w_r3    = (const float*)d_in[15];
    const float* att3    = (const float*)d_in[16];
    const float* ln3_g   = (const float*)d_in[17];
    const float* ln3_b   = (const float*)d_in[18];
    const float* rtt_w1  = (const float*)d_in[19];
    const float* rtt_b1  = (const float*)d_in[20];
    const float* rtt_w2  = (const float*)d_in[21];
    const float* rtt_b2  = (const float*)d_in[22];
    const float* ret_w1  = (const float*)d_in[23];
    const float* ret_b1  = (const float*)d_in[24];
    const float* ret_w2  = (const float*)d_in[25];
    const float* ret_b2  = (const float*)d_in[26];
    float* out = (float*)d_out;

    __nv_bfloat16 *hh, *hl, *wh, *wl;
    float *xl, *xr;
    int *deg, *off, *cur, *csr;
    cudaGetSymbolAddress((void**)&hh,  g_hh);
    cudaGetSymbolAddress((void**)&hl,  g_hl);
    cudaGetSymbolAddress((void**)&wh,  g_wh);
    cudaGetSymbolAddress((void**)&wl,  g_wl);
    cudaGetSymbolAddress((void**)&xl,  g_xl);
    cudaGetSymbolAddress((void**)&xr,  g_xr);
    cudaGetSymbolAddress((void**)&deg, g_deg);
    cudaGetSymbolAddress((void**)&off, g_off);
    cudaGetSymbolAddress((void**)&cur, g_cur);
    cudaGetSymbolAddress((void**)&csr, g_csr);

    const int SMEM128 = (4 * 5120 + 4 * 4352) * 2;   // 75776 B
    const int SMEM64  = (4 * 5120 + 4 * 2304) * 2;   // 59392 B
    cudaFuncSetAttribute(gemm_bf16_kernel<128>,
                         cudaFuncAttributeMaxDynamicSharedMemorySize, SMEM128);
    cudaFuncSetAttribute(gemm_bf16_kernel<64>,
                         cudaFuncAttributeMaxDynamicSharedMemorySize, SMEM64);

    const int TB = 256;
    const int GTB = 128;
    int nodeBlocks  = (NN * 32 + TB - 1) / TB;
    int gatBlocks   = (NN * 32 + GTB - 1) / GTB;
    int nBlocksN    = (NN + TB - 1) / TB;
    int nBlocksE    = (ETT + TB - 1) / TB;
    dim3 gGemm(MPAD / 128, 2);

    WSrcs ws;
    ws.p[0] = w_l1; ws.p[1] = w_r1; ws.p[2] = w_l2; ws.p[3] = w_r2;
    ws.p[4] = w_l3; ws.p[5] = w_r3; ws.p[6] = rtt_w1; ws.p[7] = ret_w1;

    // launch order keeps gemm L0 at my-index 3 (= profiled launch).
    split_w_all_kernel<<<(WTOT + TB - 1) / TB, TB>>>(ws, wh, wl);            // 0
    ln_in_kernel<<<nodeBlocks, TB>>>(x, ln_in_g, ln_in_b, hh, hl);           // 1
    zero_int_kernel<<<nBlocksN, TB>>>(deg, NN);                              // 2
    gemm_bf16_kernel<128><<<gGemm, TB, SMEM128>>>(hh, hl, wh, wl,            // 3
                                                  OFF_WL1, OFF_WR1, xl, xr, 64, 128);

    // CSR build (graph shared by all 3 layers)
    degree_kernel<<<nBlocksE, TB>>>(ei, deg);
    scan_kernel<<<1, 1024>>>(deg, off, cur, NN);
    scatter_kernel<<<nBlocksE, TB>>>(ei, cur, csr);

    // layer 0 tail: fused GAT+LN (no residual, relu)
    gat_ln_kernel<4><<<gatBlocks, GTB>>>(xl, xr, att1, off, csr, hh, hl,
                                         ln1_g, ln1_b, 0.0f, 1);

    // layer 1: 128 -> 128, 4 heads, residual 0.1, relu
    gemm_bf16_kernel<128><<<gGemm, TB, SMEM128>>>(hh, hl, wh, wl,
                                                  OFF_WL2, OFF_WR2, xl, xr, 128, 128);
    gat_ln_kernel<4><<<gatBlocks, GTB>>>(xl, xr, att2, off, csr, hh, hl,
                                         ln2_g, ln2_b, 0.1f, 1);

    // layer 2: 128 -> 128, 1 head, residual 0.1, no relu
    gemm_bf16_kernel<128><<<gGemm, TB, SMEM128>>>(hh, hl, wh, wl,
                                                  OFF_WL3, OFF_WR3, xl, xr, 128, 128);
    gat_ln_kernel<1><<<gatBlocks, GTB>>>(xl, xr, att3, off, csr, hh, hl,
                                         ln3_g, ln3_b, 0.1f, 0);

    // prediction heads
    gemm_bf16_kernel<64><<<gGemm, TB, SMEM64>>>(hh, hl, wh, wl,
                                                OFF_RTT, OFF_RET, xl, xr, 128, 64);
    head_kernel<<<nodeBlocks, TB>>>(xl, xr, rtt_b1, rtt_w2, rtt_b2,
                                    ret_b1, ret_w2, ret_b2, out);
}